// round 12
// baseline (speedup 1.0000x reference)
#include <cuda_runtime.h>
#include <cuda_fp16.h>
#include <math.h>

// Problem constants
#define B_  64
#define IC_ 2048
#define ID_ 16
#define K_  1024           // NC*CD = 64*16

// ---------------- device scratch (no allocations allowed) ------------------
__device__ __half g_uhat[(size_t)B_ * IC_ * K_]; // 256 MB  [b][i][k], fp16
__device__ float  g_s[3][B_ * K_];               // s per routing iteration
__device__ float  g_v0[B_ * K_];
__device__ float  g_v1[B_ * K_];

// ---------------- f32x2 packed helpers (Blackwell) -------------------------
__device__ __forceinline__ unsigned long long pack2(float lo, float hi) {
    unsigned long long r;
    asm("mov.b64 %0, {%1, %2};" : "=l"(r) : "f"(lo), "f"(hi));
    return r;
}
__device__ __forceinline__ unsigned long long fma2(unsigned long long a,
                                                   unsigned long long b,
                                                   unsigned long long c) {
    unsigned long long d;
    asm("fma.rn.f32x2 %0, %1, %2, %3;" : "=l"(d) : "l"(a), "l"(b), "l"(c));
    return d;
}
__device__ __forceinline__ unsigned long long add2(unsigned long long a,
                                                   unsigned long long b) {
    unsigned long long d;
    asm("add.rn.f32x2 %0, %1, %2;" : "=l"(d) : "l"(a), "l"(b));
    return d;
}
__device__ __forceinline__ void unpack2(unsigned long long v, float& lo, float& hi) {
    asm("mov.b64 {%0, %1}, %2;" : "=f"(lo), "=f"(hi) : "l"(v));
}

// ---------------- kernel 0: s[0..2] <- bias broadcast ----------------------
__global__ __launch_bounds__(1024) void k_init(const float* __restrict__ bias) {
    const int blk = blockIdx.x;                    // 192 blocks: 3 bufs x 64 b
    g_s[blk >> 6][(blk & 63) * K_ + threadIdx.x] = bias[threadIdx.x];
}

// ---------------- kernel 1: projection + fused iter-0 mean (R4 version) ----
#define KC    512
#define BG    32
#define ISEG  32
__global__ __launch_bounds__(256, 2) void k_project(const float* __restrict__ x,
                                                    const float* __restrict__ W) {
    const int t     = threadIdx.x;
    const int kbase = blockIdx.x * KC;
    const int bbase = blockIdx.y * BG;
    const int i0    = blockIdx.z * ISEG;
    const int k2    = kbase + 2 * t;

    __shared__ float xs[BG][16][ID_];              // 32 KB, reused per half

    unsigned long long acc[BG];
    #pragma unroll
    for (int b = 0; b < BG; b++) acc[b] = 0ull;

    for (int half = 0; half < 2; half++) {
        __syncthreads();
        for (int r = t; r < 2048; r += 256) {
            const int b   = r >> 6;
            const int rem = r & 63;
            const int ii  = rem >> 2, q = rem & 3;
            const float4 v = *(const float4*)(x +
                ((size_t)(bbase + b) * IC_ + (i0 + half * 16 + ii)) * ID_ + q * 4);
            *(float4*)&xs[b][ii][q * 4] = v;
        }
        __syncthreads();

        #pragma unroll 1
        for (int ii = 0; ii < 16; ii++) {
            const int i = i0 + half * 16 + ii;
            const float* Wi = W + (size_t)i * ID_ * K_ + k2;
            unsigned long long w[16];
            #pragma unroll
            for (int j = 0; j < 16; j++)
                w[j] = *(const unsigned long long*)(Wi + (size_t)j * K_);

            #pragma unroll 4
            for (int b = 0; b < BG; b++) {
                unsigned long long a = 0ull;
                #pragma unroll
                for (int jq = 0; jq < 4; jq++) {
                    const float4 xv = *(const float4*)&xs[b][ii][jq * 4];
                    a = fma2(w[jq * 4 + 0], pack2(xv.x, xv.x), a);
                    a = fma2(w[jq * 4 + 1], pack2(xv.y, xv.y), a);
                    a = fma2(w[jq * 4 + 2], pack2(xv.z, xv.z), a);
                    a = fma2(w[jq * 4 + 3], pack2(xv.w, xv.w), a);
                }
                float lo, hi;
                unpack2(a, lo, hi);
                *(__half2*)(g_uhat +
                    ((size_t)(bbase + b) * IC_ + i) * K_ + k2) =
                    __floats2half2_rn(lo, hi);
                acc[b] = add2(acc[b], a);
            }
        }
    }

    const float sc = 1.0f / 64.0f;                 // softmax(0) weight
    #pragma unroll 4
    for (int b = 0; b < BG; b++) {
        float lo, hi;
        unpack2(acc[b], lo, hi);
        float* sp = g_s[0] + (bbase + b) * K_ + k2;
        atomicAdd(sp,     lo * sc);
        atomicAdd(sp + 1, hi * sc);
    }
}

// ---------------- kernel 2: squash(s[it]) -> v0/v1/out ---------------------
__global__ __launch_bounds__(1024) void k_squash(int it, float* __restrict__ outbuf) {
    const int b = blockIdx.x, t = threadIdx.x;
    float sv = g_s[it][b * K_ + t];
    float sq = sv * sv;
    #pragma unroll
    for (int off = 8; off >= 1; off >>= 1)
        sq += __shfl_xor_sync(0xffffffffu, sq, off, 16);
    const float tt = sq + 1e-7f;
    const float norm = sqrtf(tt);
    const float f = tt / (1.0f + tt) / norm;
    float* dst = (it == 0) ? g_v0 : (it == 1 ? g_v1 : outbuf);
    dst[b * K_ + t] = f * sv;
}

// ---------------- kernel 3: routing pass, 4-i unrolled direct LDG ----------
// grid = (16, 64 b), block = 64 (2 autonomous warps). Warp task = 64 i's,
// processed 4 per iteration: all 16 LDG.128 issued up front (MLP=16/warp),
// then convert + softmax row-by-row (u temporaries reused; only the 16 raw
// uint4 stay live). Lane owns capsules n0=lane, n1=lane+32.
template <bool SECOND>
__global__ __launch_bounds__(64) void k_route() {
    const int b    = blockIdx.y;
    const int wt   = blockIdx.x * 2 + (threadIdx.x >> 5);
    const int lane = threadIdx.x & 31;
    const int i0   = wt * 64;

    float vA[16], vB[16];
    {
        const float4* vp = (const float4*)(g_v0 + b * K_);
        #pragma unroll
        for (int q = 0; q < 4; q++) {
            float4 a = vp[lane * 4 + q];
            vA[4*q] = a.x; vA[4*q+1] = a.y; vA[4*q+2] = a.z; vA[4*q+3] = a.w;
            float4 c = vp[(lane + 32) * 4 + q];
            vB[4*q] = c.x; vB[4*q+1] = c.y; vB[4*q+2] = c.z; vB[4*q+3] = c.w;
        }
        if (SECOND) {
            const float4* vq = (const float4*)(g_v1 + b * K_);
            #pragma unroll
            for (int q = 0; q < 4; q++) {
                float4 a = vq[lane * 4 + q];
                vA[4*q] += a.x; vA[4*q+1] += a.y; vA[4*q+2] += a.z; vA[4*q+3] += a.w;
                float4 c = vq[(lane + 32) * 4 + q];
                vB[4*q] += c.x; vB[4*q+1] += c.y; vB[4*q+2] += c.z; vB[4*q+3] += c.w;
            }
        }
    }

    const uint4* base = (const uint4*)(g_uhat + ((size_t)b * IC_ + i0) * K_);
    const int ROWQ = K_ / 8;                       // uint4 per i-row (fp16)

    float sA[16], sB[16];
    #pragma unroll
    for (int q = 0; q < 16; q++) { sA[q] = 0.f; sB[q] = 0.f; }

    #pragma unroll 1
    for (int it = 0; it < 16; it++) {              // 4 i per iteration
        const uint4* r = base + (size_t)(4 * it) * ROWQ;
        // 16 front-batched LDG.128 (rows it*4 .. it*4+3)
        uint4 L[16];
        #pragma unroll
        for (int row = 0; row < 4; row++) {
            const uint4* rr = r + row * ROWQ;
            L[row * 4 + 0] = rr[lane * 2];
            L[row * 4 + 1] = rr[lane * 2 + 1];
            L[row * 4 + 2] = rr[64 + lane * 2];
            L[row * 4 + 3] = rr[64 + lane * 2 + 1];
        }

        #pragma unroll
        for (int row = 0; row < 4; row++) {
            float uA[16], uB[16];
            {
                const __half2* h; float2 f;
                h = (const __half2*)&L[row * 4 + 0];
                #pragma unroll
                for (int q = 0; q < 4; q++) { f = __half22float2(h[q]); uA[2*q] = f.x; uA[2*q+1] = f.y; }
                h = (const __half2*)&L[row * 4 + 1];
                #pragma unroll
                for (int q = 0; q < 4; q++) { f = __half22float2(h[q]); uA[8+2*q] = f.x; uA[8+2*q+1] = f.y; }
                h = (const __half2*)&L[row * 4 + 2];
                #pragma unroll
                for (int q = 0; q < 4; q++) { f = __half22float2(h[q]); uB[2*q] = f.x; uB[2*q+1] = f.y; }
                h = (const __half2*)&L[row * 4 + 3];
                #pragma unroll
                for (int q = 0; q < 4; q++) { f = __half22float2(h[q]); uB[8+2*q] = f.x; uB[8+2*q+1] = f.y; }
            }

            float a0 = 0.f, a1 = 0.f;
            #pragma unroll
            for (int q = 0; q < 16; q++) {
                a0 = fmaf(uA[q], vA[q], a0);
                a1 = fmaf(uB[q], vB[q], a1);
            }

            const float e0 = __expf(a0);
            const float e1 = __expf(a1);
            float z = e0 + e1;
            #pragma unroll
            for (int off = 16; off >= 1; off >>= 1)
                z += __shfl_xor_sync(0xffffffffu, z, off);
            const float rz = __fdividef(1.0f, z);
            const float c0 = e0 * rz, c1 = e1 * rz;

            #pragma unroll
            for (int q = 0; q < 16; q++) {
                sA[q] = fmaf(c0, uA[q], sA[q]);
                sB[q] = fmaf(c1, uB[q], sB[q]);
            }
        }
    }

    float* sp = g_s[SECOND ? 2 : 1] + b * K_;
    #pragma unroll
    for (int q = 0; q < 16; q++) {
        atomicAdd(sp + lane * 16 + q, sA[q]);
        atomicAdd(sp + (lane + 32) * 16 + q, sB[q]);
    }
}

// ---------------- launcher -------------------------------------------------
extern "C" void kernel_launch(void* const* d_in, const int* in_sizes, int n_in,
                              void* d_out, int out_size) {
    const float* x    = (const float*)d_in[0];   // [64,2048,16]
    const float* W    = (const float*)d_in[1];   // [2048,16,1024]
    const float* bias = (const float*)d_in[2];   // [64,16] -> 1024
    float* out = (float*)d_out;                  // [64,64,16]

    k_init<<<192, 1024>>>(bias);                         // s0,s1,s2 = bias
    k_project<<<dim3(2, 2, 64), 256>>>(x, W);            // u_hat(fp16) + s0 mean
    k_squash<<<B_, 1024>>>(0, out);                      // v0

    k_route<false><<<dim3(16, B_), 64>>>();              // s1
    k_squash<<<B_, 1024>>>(1, out);                      // v1

    k_route<true><<<dim3(16, B_), 64>>>();               // s2
    k_squash<<<B_, 1024>>>(2, out);                      // v2 -> out
}

// round 13
// speedup vs baseline: 1.0509x; 1.0509x over previous
#include <cuda_runtime.h>
#include <cuda_fp16.h>
#include <math.h>

// Problem constants
#define B_  64
#define IC_ 2048
#define ID_ 16
#define K_  1024           // NC*CD = 64*16

// ---------------- device scratch (no allocations allowed) ------------------
__device__ __half g_uhat[(size_t)B_ * IC_ * K_]; // 256 MB  [b][i][k], fp16
__device__ float  g_s[3][B_ * K_];               // s per routing iteration
__device__ float  g_v0[B_ * K_];
__device__ float  g_v1[B_ * K_];

// ---------------- f32x2 packed helpers (Blackwell) -------------------------
__device__ __forceinline__ unsigned long long pack2(float lo, float hi) {
    unsigned long long r;
    asm("mov.b64 %0, {%1, %2};" : "=l"(r) : "f"(lo), "f"(hi));
    return r;
}
__device__ __forceinline__ unsigned long long fma2(unsigned long long a,
                                                   unsigned long long b,
                                                   unsigned long long c) {
    unsigned long long d;
    asm("fma.rn.f32x2 %0, %1, %2, %3;" : "=l"(d) : "l"(a), "l"(b), "l"(c));
    return d;
}
__device__ __forceinline__ unsigned long long add2(unsigned long long a,
                                                   unsigned long long b) {
    unsigned long long d;
    asm("add.rn.f32x2 %0, %1, %2;" : "=l"(d) : "l"(a), "l"(b));
    return d;
}
__device__ __forceinline__ void unpack2(unsigned long long v, float& lo, float& hi) {
    asm("mov.b64 {%0, %1}, %2;" : "=f"(lo), "=f"(hi) : "l"(v));
}

// ---------------- kernel 0: s[0..2] <- bias broadcast ----------------------
__global__ __launch_bounds__(1024) void k_init(const float* __restrict__ bias) {
    const int blk = blockIdx.x;                    // 192 blocks: 3 bufs x 64 b
    g_s[blk >> 6][(blk & 63) * K_ + threadIdx.x] = bias[threadIdx.x];
}

// ---------------- kernel 1: projection + fused iter-0 mean (R4 version) ----
#define KC    512
#define BG    32
#define ISEG  32
__global__ __launch_bounds__(256, 2) void k_project(const float* __restrict__ x,
                                                    const float* __restrict__ W) {
    const int t     = threadIdx.x;
    const int kbase = blockIdx.x * KC;
    const int bbase = blockIdx.y * BG;
    const int i0    = blockIdx.z * ISEG;
    const int k2    = kbase + 2 * t;

    __shared__ float xs[BG][16][ID_];              // 32 KB, reused per half

    unsigned long long acc[BG];
    #pragma unroll
    for (int b = 0; b < BG; b++) acc[b] = 0ull;

    for (int half = 0; half < 2; half++) {
        __syncthreads();
        for (int r = t; r < 2048; r += 256) {
            const int b   = r >> 6;
            const int rem = r & 63;
            const int ii  = rem >> 2, q = rem & 3;
            const float4 v = *(const float4*)(x +
                ((size_t)(bbase + b) * IC_ + (i0 + half * 16 + ii)) * ID_ + q * 4);
            *(float4*)&xs[b][ii][q * 4] = v;
        }
        __syncthreads();

        #pragma unroll 1
        for (int ii = 0; ii < 16; ii++) {
            const int i = i0 + half * 16 + ii;
            const float* Wi = W + (size_t)i * ID_ * K_ + k2;
            unsigned long long w[16];
            #pragma unroll
            for (int j = 0; j < 16; j++)
                w[j] = *(const unsigned long long*)(Wi + (size_t)j * K_);

            #pragma unroll 4
            for (int b = 0; b < BG; b++) {
                unsigned long long a = 0ull;
                #pragma unroll
                for (int jq = 0; jq < 4; jq++) {
                    const float4 xv = *(const float4*)&xs[b][ii][jq * 4];
                    a = fma2(w[jq * 4 + 0], pack2(xv.x, xv.x), a);
                    a = fma2(w[jq * 4 + 1], pack2(xv.y, xv.y), a);
                    a = fma2(w[jq * 4 + 2], pack2(xv.z, xv.z), a);
                    a = fma2(w[jq * 4 + 3], pack2(xv.w, xv.w), a);
                }
                float lo, hi;
                unpack2(a, lo, hi);
                *(__half2*)(g_uhat +
                    ((size_t)(bbase + b) * IC_ + i) * K_ + k2) =
                    __floats2half2_rn(lo, hi);
                acc[b] = add2(acc[b], a);
            }
        }
    }

    const float sc = 1.0f / 64.0f;                 // softmax(0) weight
    #pragma unroll 4
    for (int b = 0; b < BG; b++) {
        float lo, hi;
        unpack2(acc[b], lo, hi);
        float* sp = g_s[0] + (bbase + b) * K_ + k2;
        atomicAdd(sp,     lo * sc);
        atomicAdd(sp + 1, hi * sc);
    }
}

// ---------------- kernel 2: squash(s[it]) -> v0/v1/out ---------------------
__global__ __launch_bounds__(1024) void k_squash(int it, float* __restrict__ outbuf) {
    const int b = blockIdx.x, t = threadIdx.x;
    float sv = g_s[it][b * K_ + t];
    float sq = sv * sv;
    #pragma unroll
    for (int off = 8; off >= 1; off >>= 1)
        sq += __shfl_xor_sync(0xffffffffu, sq, off, 16);
    const float tt = sq + 1e-7f;
    const float norm = sqrtf(tt);
    const float f = tt / (1.0f + tt) / norm;
    float* dst = (it == 0) ? g_v0 : (it == 1 ? g_v1 : outbuf);
    dst[b * K_ + t] = f * sv;
}

// ---------------- route helpers --------------------------------------------
// process one i-row (4 uint4 of fp16) : agreement dot, 64-wide softmax
// weight, accumulate c*u into sA/sB. Consumes the uint4s by value.
__device__ __forceinline__ void route_row(uint4 hA0, uint4 hA1,
                                          uint4 hB0, uint4 hB1,
                                          const float* __restrict__ vA,
                                          const float* __restrict__ vB,
                                          float* __restrict__ sA,
                                          float* __restrict__ sB) {
    float uA[16], uB[16];
    {
        const __half2* h; float2 f;
        h = (const __half2*)&hA0;
        #pragma unroll
        for (int q = 0; q < 4; q++) { f = __half22float2(h[q]); uA[2*q] = f.x; uA[2*q+1] = f.y; }
        h = (const __half2*)&hA1;
        #pragma unroll
        for (int q = 0; q < 4; q++) { f = __half22float2(h[q]); uA[8+2*q] = f.x; uA[8+2*q+1] = f.y; }
        h = (const __half2*)&hB0;
        #pragma unroll
        for (int q = 0; q < 4; q++) { f = __half22float2(h[q]); uB[2*q] = f.x; uB[2*q+1] = f.y; }
        h = (const __half2*)&hB1;
        #pragma unroll
        for (int q = 0; q < 4; q++) { f = __half22float2(h[q]); uB[8+2*q] = f.x; uB[8+2*q+1] = f.y; }
    }

    float a0 = 0.f, a1 = 0.f;
    #pragma unroll
    for (int q = 0; q < 16; q++) {
        a0 = fmaf(uA[q], vA[q], a0);
        a1 = fmaf(uB[q], vB[q], a1);
    }

    const float e0 = __expf(a0);
    const float e1 = __expf(a1);
    float z = e0 + e1;
    #pragma unroll
    for (int off = 16; off >= 1; off >>= 1)
        z += __shfl_xor_sync(0xffffffffu, z, off);
    const float rz = __fdividef(1.0f, z);
    const float c0 = e0 * rz, c1 = e1 * rz;

    #pragma unroll
    for (int q = 0; q < 16; q++) {
        sA[q] = fmaf(c0, uA[q], sA[q]);
        sB[q] = fmaf(c1, uB[q], sB[q]);
    }
}

// ---------------- kernel 3: routing pass, 4-i batch, named scalars ---------
// grid = (16, 64 b), block = 64 (2 autonomous warps). Warp task = 64 i's,
// processed 4 per iteration: 16 individually-NAMED __ldcs LDG.128 issued up
// front (no array indexing -> no local spill), then rows processed in order.
// Lane owns capsules n0=lane, n1=lane+32.
template <bool SECOND>
__global__ __launch_bounds__(64) void k_route() {
    const int b    = blockIdx.y;
    const int wt   = blockIdx.x * 2 + (threadIdx.x >> 5);
    const int lane = threadIdx.x & 31;
    const int i0   = wt * 64;

    float vA[16], vB[16];
    {
        const float4* vp = (const float4*)(g_v0 + b * K_);
        #pragma unroll
        for (int q = 0; q < 4; q++) {
            float4 a = vp[lane * 4 + q];
            vA[4*q] = a.x; vA[4*q+1] = a.y; vA[4*q+2] = a.z; vA[4*q+3] = a.w;
            float4 c = vp[(lane + 32) * 4 + q];
            vB[4*q] = c.x; vB[4*q+1] = c.y; vB[4*q+2] = c.z; vB[4*q+3] = c.w;
        }
        if (SECOND) {
            const float4* vq = (const float4*)(g_v1 + b * K_);
            #pragma unroll
            for (int q = 0; q < 4; q++) {
                float4 a = vq[lane * 4 + q];
                vA[4*q] += a.x; vA[4*q+1] += a.y; vA[4*q+2] += a.z; vA[4*q+3] += a.w;
                float4 c = vq[(lane + 32) * 4 + q];
                vB[4*q] += c.x; vB[4*q+1] += c.y; vB[4*q+2] += c.z; vB[4*q+3] += c.w;
            }
        }
    }

    const uint4* base = (const uint4*)(g_uhat + ((size_t)b * IC_ + i0) * K_);
    const int ROWQ = K_ / 8;                       // uint4 per i-row (fp16)

    float sA[16], sB[16];
    #pragma unroll
    for (int q = 0; q < 16; q++) { sA[q] = 0.f; sB[q] = 0.f; }

    #pragma unroll 1
    for (int it = 0; it < 16; it++) {              // 4 i per iteration
        const uint4* r0 = base + (size_t)(4 * it) * ROWQ;
        const uint4* r1 = r0 + ROWQ;
        const uint4* r2 = r1 + ROWQ;
        const uint4* r3 = r2 + ROWQ;

        // 16 front-batched streaming loads, all individually named
        uint4 p0A0 = __ldcs(r0 + lane * 2);
        uint4 p0A1 = __ldcs(r0 + lane * 2 + 1);
        uint4 p0B0 = __ldcs(r0 + 64 + lane * 2);
        uint4 p0B1 = __ldcs(r0 + 64 + lane * 2 + 1);
        uint4 p1A0 = __ldcs(r1 + lane * 2);
        uint4 p1A1 = __ldcs(r1 + lane * 2 + 1);
        uint4 p1B0 = __ldcs(r1 + 64 + lane * 2);
        uint4 p1B1 = __ldcs(r1 + 64 + lane * 2 + 1);
        uint4 p2A0 = __ldcs(r2 + lane * 2);
        uint4 p2A1 = __ldcs(r2 + lane * 2 + 1);
        uint4 p2B0 = __ldcs(r2 + 64 + lane * 2);
        uint4 p2B1 = __ldcs(r2 + 64 + lane * 2 + 1);
        uint4 p3A0 = __ldcs(r3 + lane * 2);
        uint4 p3A1 = __ldcs(r3 + lane * 2 + 1);
        uint4 p3B0 = __ldcs(r3 + 64 + lane * 2);
        uint4 p3B1 = __ldcs(r3 + 64 + lane * 2 + 1);

        route_row(p0A0, p0A1, p0B0, p0B1, vA, vB, sA, sB);
        route_row(p1A0, p1A1, p1B0, p1B1, vA, vB, sA, sB);
        route_row(p2A0, p2A1, p2B0, p2B1, vA, vB, sA, sB);
        route_row(p3A0, p3A1, p3B0, p3B1, vA, vB, sA, sB);
    }

    float* sp = g_s[SECOND ? 2 : 1] + b * K_;
    #pragma unroll
    for (int q = 0; q < 16; q++) {
        atomicAdd(sp + lane * 16 + q, sA[q]);
        atomicAdd(sp + (lane + 32) * 16 + q, sB[q]);
    }
}

// ---------------- launcher -------------------------------------------------
extern "C" void kernel_launch(void* const* d_in, const int* in_sizes, int n_in,
                              void* d_out, int out_size) {
    const float* x    = (const float*)d_in[0];   // [64,2048,16]
    const float* W    = (const float*)d_in[1];   // [2048,16,1024]
    const float* bias = (const float*)d_in[2];   // [64,16] -> 1024
    float* out = (float*)d_out;                  // [64,64,16]

    k_init<<<192, 1024>>>(bias);                         // s0,s1,s2 = bias
    k_project<<<dim3(2, 2, 64), 256>>>(x, W);            // u_hat(fp16) + s0 mean
    k_squash<<<B_, 1024>>>(0, out);                      // v0

    k_route<false><<<dim3(16, B_), 64>>>();              // s1
    k_squash<<<B_, 1024>>>(1, out);                      // v1

    k_route<true><<<dim3(16, B_), 64>>>();               // s2
    k_squash<<<B_, 1024>>>(2, out);                      // v2 -> out
}

// round 14
// speedup vs baseline: 1.0971x; 1.0439x over previous
#include <cuda_runtime.h>
#include <cuda_fp16.h>
#include <math.h>

// Problem constants
#define B_  64
#define IC_ 2048
#define ID_ 16
#define K_  1024           // NC*CD = 64*16

// ---------------- device scratch (no allocations allowed) ------------------
__device__ __half g_uhat[(size_t)B_ * IC_ * K_]; // 256 MB  [b][i][k], fp16
__device__ float  g_s[3][B_ * K_];               // s per routing iteration
__device__ float  g_v0[B_ * K_];
__device__ float  g_v1[B_ * K_];

// ---------------- f32x2 packed helpers (Blackwell) -------------------------
__device__ __forceinline__ unsigned long long pack2(float lo, float hi) {
    unsigned long long r;
    asm("mov.b64 %0, {%1, %2};" : "=l"(r) : "f"(lo), "f"(hi));
    return r;
}
__device__ __forceinline__ unsigned long long fma2(unsigned long long a,
                                                   unsigned long long b,
                                                   unsigned long long c) {
    unsigned long long d;
    asm("fma.rn.f32x2 %0, %1, %2, %3;" : "=l"(d) : "l"(a), "l"(b), "l"(c));
    return d;
}
__device__ __forceinline__ unsigned long long add2(unsigned long long a,
                                                   unsigned long long b) {
    unsigned long long d;
    asm("add.rn.f32x2 %0, %1, %2;" : "=l"(d) : "l"(a), "l"(b));
    return d;
}
__device__ __forceinline__ void unpack2(unsigned long long v, float& lo, float& hi) {
    asm("mov.b64 {%0, %1}, %2;" : "=f"(lo), "=f"(hi) : "l"(v));
}

// ---------------- kernel 0: s[0..2] <- bias broadcast ----------------------
__global__ __launch_bounds__(1024) void k_init(const float* __restrict__ bias) {
    const int blk = blockIdx.x;                    // 192 blocks: 3 bufs x 64 b
    g_s[blk >> 6][(blk & 63) * K_ + threadIdx.x] = bias[threadIdx.x];
}

// ---------------- kernel 1: projection + fused iter-0 mean (R4 version) ----
#define KC    512
#define BG    32
#define ISEG  32
__global__ __launch_bounds__(256, 2) void k_project(const float* __restrict__ x,
                                                    const float* __restrict__ W) {
    const int t     = threadIdx.x;
    const int kbase = blockIdx.x * KC;
    const int bbase = blockIdx.y * BG;
    const int i0    = blockIdx.z * ISEG;
    const int k2    = kbase + 2 * t;

    __shared__ float xs[BG][16][ID_];              // 32 KB, reused per half

    unsigned long long acc[BG];
    #pragma unroll
    for (int b = 0; b < BG; b++) acc[b] = 0ull;

    for (int half = 0; half < 2; half++) {
        __syncthreads();
        for (int r = t; r < 2048; r += 256) {
            const int b   = r >> 6;
            const int rem = r & 63;
            const int ii  = rem >> 2, q = rem & 3;
            const float4 v = *(const float4*)(x +
                ((size_t)(bbase + b) * IC_ + (i0 + half * 16 + ii)) * ID_ + q * 4);
            *(float4*)&xs[b][ii][q * 4] = v;
        }
        __syncthreads();

        #pragma unroll 1
        for (int ii = 0; ii < 16; ii++) {
            const int i = i0 + half * 16 + ii;
            const float* Wi = W + (size_t)i * ID_ * K_ + k2;
            unsigned long long w[16];
            #pragma unroll
            for (int j = 0; j < 16; j++)
                w[j] = *(const unsigned long long*)(Wi + (size_t)j * K_);

            #pragma unroll 4
            for (int b = 0; b < BG; b++) {
                unsigned long long a = 0ull;
                #pragma unroll
                for (int jq = 0; jq < 4; jq++) {
                    const float4 xv = *(const float4*)&xs[b][ii][jq * 4];
                    a = fma2(w[jq * 4 + 0], pack2(xv.x, xv.x), a);
                    a = fma2(w[jq * 4 + 1], pack2(xv.y, xv.y), a);
                    a = fma2(w[jq * 4 + 2], pack2(xv.z, xv.z), a);
                    a = fma2(w[jq * 4 + 3], pack2(xv.w, xv.w), a);
                }
                float lo, hi;
                unpack2(a, lo, hi);
                *(__half2*)(g_uhat +
                    ((size_t)(bbase + b) * IC_ + i) * K_ + k2) =
                    __floats2half2_rn(lo, hi);
                acc[b] = add2(acc[b], a);
            }
        }
    }

    const float sc = 1.0f / 64.0f;                 // softmax(0) weight
    #pragma unroll 4
    for (int b = 0; b < BG; b++) {
        float lo, hi;
        unpack2(acc[b], lo, hi);
        float* sp = g_s[0] + (bbase + b) * K_ + k2;
        atomicAdd(sp,     lo * sc);
        atomicAdd(sp + 1, hi * sc);
    }
}

// ---------------- kernel 2: squash(s[it]) -> v0/v1/out ---------------------
__global__ __launch_bounds__(1024) void k_squash(int it, float* __restrict__ outbuf) {
    const int b = blockIdx.x, t = threadIdx.x;
    float sv = g_s[it][b * K_ + t];
    float sq = sv * sv;
    #pragma unroll
    for (int off = 8; off >= 1; off >>= 1)
        sq += __shfl_xor_sync(0xffffffffu, sq, off, 16);
    const float tt = sq + 1e-7f;
    const float norm = sqrtf(tt);
    const float f = tt / (1.0f + tt) / norm;
    float* dst = (it == 0) ? g_v0 : (it == 1 ? g_v1 : outbuf);
    dst[b * K_ + t] = f * sv;
}

// ---------------- kernel 3: routing pass, half2 datapath -------------------
// grid = (32, 64 b), block = 64 (2 autonomous warps). Warp task = 32 i's,
// 2 per iteration (8 front-batched LDG.128 / warp, the proven R11 shape).
// u stays half2: dot via HFMA2 (8/capsule), accumulate via HFMA2 into half2
// partials; fp32 only for softmax + final atomic flush.
// Lane owns capsules n0=lane, n1=lane+32.
template <bool SECOND>
__global__ __launch_bounds__(64, 8) void k_route() {
    const int b    = blockIdx.y;
    const int wt   = blockIdx.x * 2 + (threadIdx.x >> 5);
    const int lane = threadIdx.x & 31;
    const int i0   = wt * 32;

    // v rows as half2 (vA2[q] = (v[2q], v[2q+1]))
    __half2 vA2[8], vB2[8];
    {
        float vA[16], vB[16];
        const float4* vp = (const float4*)(g_v0 + b * K_);
        #pragma unroll
        for (int q = 0; q < 4; q++) {
            float4 a = vp[lane * 4 + q];
            vA[4*q] = a.x; vA[4*q+1] = a.y; vA[4*q+2] = a.z; vA[4*q+3] = a.w;
            float4 c = vp[(lane + 32) * 4 + q];
            vB[4*q] = c.x; vB[4*q+1] = c.y; vB[4*q+2] = c.z; vB[4*q+3] = c.w;
        }
        if (SECOND) {
            const float4* vq = (const float4*)(g_v1 + b * K_);
            #pragma unroll
            for (int q = 0; q < 4; q++) {
                float4 a = vq[lane * 4 + q];
                vA[4*q] += a.x; vA[4*q+1] += a.y; vA[4*q+2] += a.z; vA[4*q+3] += a.w;
                float4 c = vq[(lane + 32) * 4 + q];
                vB[4*q] += c.x; vB[4*q+1] += c.y; vB[4*q+2] += c.z; vB[4*q+3] += c.w;
            }
        }
        #pragma unroll
        for (int q = 0; q < 8; q++) {
            vA2[q] = __floats2half2_rn(vA[2*q], vA[2*q+1]);
            vB2[q] = __floats2half2_rn(vB[2*q], vB[2*q+1]);
        }
    }

    const uint4* base = (const uint4*)(g_uhat + ((size_t)b * IC_ + i0) * K_);
    const int ROWQ = K_ / 8;                       // uint4 per i-row (fp16)

    __half2 sA2[8], sB2[8];
    #pragma unroll
    for (int q = 0; q < 8; q++) {
        sA2[q] = __floats2half2_rn(0.f, 0.f);
        sB2[q] = __floats2half2_rn(0.f, 0.f);
    }

    #pragma unroll 1
    for (int it = 0; it < 16; it++) {              // 2 i per iteration
        const uint4* r0 = base + (size_t)(2 * it) * ROWQ;
        const uint4* r1 = r0 + ROWQ;
        // 8 front-batched LDG.128 (proven MLP=8 shape)
        uint4 xA0 = r0[lane * 2],      xA1 = r0[lane * 2 + 1];
        uint4 xB0 = r0[64 + lane * 2], xB1 = r0[64 + lane * 2 + 1];
        uint4 yA0 = r1[lane * 2],      yA1 = r1[lane * 2 + 1];
        uint4 yB0 = r1[64 + lane * 2], yB1 = r1[64 + lane * 2 + 1];

        #pragma unroll
        for (int half = 0; half < 2; half++) {
            const __half2* hA0 = (const __half2*)(half ? &yA0 : &xA0);
            const __half2* hA1 = (const __half2*)(half ? &yA1 : &xA1);
            const __half2* hB0 = (const __half2*)(half ? &yB0 : &xB0);
            const __half2* hB1 = (const __half2*)(half ? &yB1 : &xB1);

            // agreement dots in half2 (8 HFMA2 per capsule)
            __half2 d0 = __floats2half2_rn(0.f, 0.f);
            __half2 d1 = __floats2half2_rn(0.f, 0.f);
            #pragma unroll
            for (int q = 0; q < 4; q++) {
                d0 = __hfma2(hA0[q], vA2[q],     d0);
                d0 = __hfma2(hA1[q], vA2[4 + q], d0);
                d1 = __hfma2(hB0[q], vB2[q],     d1);
                d1 = __hfma2(hB1[q], vB2[4 + q], d1);
            }
            float2 f0 = __half22float2(d0);
            float2 f1 = __half22float2(d1);
            const float a0 = f0.x + f0.y;
            const float a1 = f1.x + f1.y;

            const float e0 = __expf(a0);
            const float e1 = __expf(a1);
            float z = e0 + e1;
            #pragma unroll
            for (int off = 16; off >= 1; off >>= 1)
                z += __shfl_xor_sync(0xffffffffu, z, off);
            const float rz = __fdividef(1.0f, z);
            const __half2 c02 = __float2half2_rn(e0 * rz);
            const __half2 c12 = __float2half2_rn(e1 * rz);

            // accumulate c*u in half2 partials (16 HFMA2)
            #pragma unroll
            for (int q = 0; q < 4; q++) {
                sA2[q]     = __hfma2(c02, hA0[q], sA2[q]);
                sA2[4 + q] = __hfma2(c02, hA1[q], sA2[4 + q]);
                sB2[q]     = __hfma2(c12, hB0[q], sB2[q]);
                sB2[4 + q] = __hfma2(c12, hB1[q], sB2[4 + q]);
            }
        }
    }

    float* sp = g_s[SECOND ? 2 : 1] + b * K_;
    #pragma unroll
    for (int q = 0; q < 8; q++) {
        float2 fa = __half22float2(sA2[q]);
        atomicAdd(sp + lane * 16 + 2 * q,     fa.x);
        atomicAdd(sp + lane * 16 + 2 * q + 1, fa.y);
        float2 fb = __half22float2(sB2[q]);
        atomicAdd(sp + (lane + 32) * 16 + 2 * q,     fb.x);
        atomicAdd(sp + (lane + 32) * 16 + 2 * q + 1, fb.y);
    }
}

// ---------------- launcher -------------------------------------------------
extern "C" void kernel_launch(void* const* d_in, const int* in_sizes, int n_in,
                              void* d_out, int out_size) {
    const float* x    = (const float*)d_in[0];   // [64,2048,16]
    const float* W    = (const float*)d_in[1];   // [2048,16,1024]
    const float* bias = (const float*)d_in[2];   // [64,16] -> 1024
    float* out = (float*)d_out;                  // [64,64,16]

    k_init<<<192, 1024>>>(bias);                         // s0,s1,s2 = bias
    k_project<<<dim3(2, 2, 64), 256>>>(x, W);            // u_hat(fp16) + s0 mean
    k_squash<<<B_, 1024>>>(0, out);                      // v0

    k_route<false><<<dim3(32, B_), 64>>>();              // s1
    k_squash<<<B_, 1024>>>(1, out);                      // v1

    k_route<true><<<dim3(32, B_), 64>>>();               // s2
    k_squash<<<B_, 1024>>>(2, out);                      // v2 -> out
}

// round 15
// speedup vs baseline: 1.2556x; 1.1445x over previous
#include <cuda_runtime.h>
#include <cuda_fp16.h>
#include <math.h>

// Problem constants
#define B_  64
#define IC_ 2048
#define ID_ 16
#define K_  1024           // NC*CD = 64*16

// ---------------- device scratch (no allocations allowed) ------------------
__device__ __half g_uhat[(size_t)B_ * IC_ * K_]; // 256 MB  [b][i][k], fp16
__device__ float  g_s[3][B_ * K_];               // s per routing iteration
__device__ float  g_v0[B_ * K_];
__device__ float  g_v1[B_ * K_];

// ---------------- f32x2 packed helpers (Blackwell) -------------------------
__device__ __forceinline__ unsigned long long pack2(float lo, float hi) {
    unsigned long long r;
    asm("mov.b64 %0, {%1, %2};" : "=l"(r) : "f"(lo), "f"(hi));
    return r;
}
__device__ __forceinline__ unsigned long long fma2(unsigned long long a,
                                                   unsigned long long b,
                                                   unsigned long long c) {
    unsigned long long d;
    asm("fma.rn.f32x2 %0, %1, %2, %3;" : "=l"(d) : "l"(a), "l"(b), "l"(c));
    return d;
}
__device__ __forceinline__ unsigned long long add2(unsigned long long a,
                                                   unsigned long long b) {
    unsigned long long d;
    asm("add.rn.f32x2 %0, %1, %2;" : "=l"(d) : "l"(a), "l"(b));
    return d;
}
__device__ __forceinline__ void unpack2(unsigned long long v, float& lo, float& hi) {
    asm("mov.b64 {%0, %1}, %2;" : "=f"(lo), "=f"(hi) : "l"(v));
}

// ---------------- kernel 0: s[0..2] <- bias broadcast ----------------------
__global__ __launch_bounds__(1024) void k_init(const float* __restrict__ bias) {
    const int blk = blockIdx.x;                    // 192 blocks: 3 bufs x 64 b
    g_s[blk >> 6][(blk & 63) * K_ + threadIdx.x] = bias[threadIdx.x];
}

// ---------------- kernel 1: projection + fused iter-0 mean (R4 version) ----
#define KC    512
#define BG    32
#define ISEG  32
__global__ __launch_bounds__(256, 2) void k_project(const float* __restrict__ x,
                                                    const float* __restrict__ W) {
    const int t     = threadIdx.x;
    const int kbase = blockIdx.x * KC;
    const int bbase = blockIdx.y * BG;
    const int i0    = blockIdx.z * ISEG;
    const int k2    = kbase + 2 * t;

    __shared__ float xs[BG][16][ID_];              // 32 KB, reused per half

    unsigned long long acc[BG];
    #pragma unroll
    for (int b = 0; b < BG; b++) acc[b] = 0ull;

    for (int half = 0; half < 2; half++) {
        __syncthreads();
        for (int r = t; r < 2048; r += 256) {
            const int b   = r >> 6;
            const int rem = r & 63;
            const int ii  = rem >> 2, q = rem & 3;
            const float4 v = *(const float4*)(x +
                ((size_t)(bbase + b) * IC_ + (i0 + half * 16 + ii)) * ID_ + q * 4);
            *(float4*)&xs[b][ii][q * 4] = v;
        }
        __syncthreads();

        #pragma unroll 1
        for (int ii = 0; ii < 16; ii++) {
            const int i = i0 + half * 16 + ii;
            const float* Wi = W + (size_t)i * ID_ * K_ + k2;
            unsigned long long w[16];
            #pragma unroll
            for (int j = 0; j < 16; j++)
                w[j] = *(const unsigned long long*)(Wi + (size_t)j * K_);

            #pragma unroll 4
            for (int b = 0; b < BG; b++) {
                unsigned long long a = 0ull;
                #pragma unroll
                for (int jq = 0; jq < 4; jq++) {
                    const float4 xv = *(const float4*)&xs[b][ii][jq * 4];
                    a = fma2(w[jq * 4 + 0], pack2(xv.x, xv.x), a);
                    a = fma2(w[jq * 4 + 1], pack2(xv.y, xv.y), a);
                    a = fma2(w[jq * 4 + 2], pack2(xv.z, xv.z), a);
                    a = fma2(w[jq * 4 + 3], pack2(xv.w, xv.w), a);
                }
                float lo, hi;
                unpack2(a, lo, hi);
                *(__half2*)(g_uhat +
                    ((size_t)(bbase + b) * IC_ + i) * K_ + k2) =
                    __floats2half2_rn(lo, hi);
                acc[b] = add2(acc[b], a);
            }
        }
    }

    const float sc = 1.0f / 64.0f;                 // softmax(0) weight
    #pragma unroll 4
    for (int b = 0; b < BG; b++) {
        float lo, hi;
        unpack2(acc[b], lo, hi);
        float* sp = g_s[0] + (bbase + b) * K_ + k2;
        atomicAdd(sp,     lo * sc);
        atomicAdd(sp + 1, hi * sc);
    }
}

// ---------------- kernel 2: squash(s[it]) -> v0/v1/out ---------------------
__global__ __launch_bounds__(1024) void k_squash(int it, float* __restrict__ outbuf) {
    const int b = blockIdx.x, t = threadIdx.x;
    float sv = g_s[it][b * K_ + t];
    float sq = sv * sv;
    #pragma unroll
    for (int off = 8; off >= 1; off >>= 1)
        sq += __shfl_xor_sync(0xffffffffu, sq, off, 16);
    const float tt = sq + 1e-7f;
    const float norm = sqrtf(tt);
    const float f = tt / (1.0f + tt) / norm;
    float* dst = (it == 0) ? g_v0 : (it == 1 ? g_v1 : outbuf);
    dst[b * K_ + t] = f * sv;
}

// ---------------- kernel 3: routing pass, half2 + pair prefetch ------------
// grid = (16, 64 b), block = 64 (2 autonomous warps). Warp task = 64 i's,
// 2 per iteration. Each iteration PREFETCHES the next 2-row pair (8 named
// uint4) before processing the current pair, so 8 LDG.128 stay in flight
// during the softmax shuffle chains (which are interleaved for 2x ILP).
// u stays half2 end-to-end; fp32 only for softmax + final atomic flush.
template <bool SECOND>
__global__ __launch_bounds__(64, 8) void k_route() {
    const int b    = blockIdx.y;
    const int wt   = blockIdx.x * 2 + (threadIdx.x >> 5);
    const int lane = threadIdx.x & 31;
    const int i0   = wt * 64;

    // v rows as half2 (vA2[q] = (v[2q], v[2q+1]))
    __half2 vA2[8], vB2[8];
    {
        float vA[16], vB[16];
        const float4* vp = (const float4*)(g_v0 + b * K_);
        #pragma unroll
        for (int q = 0; q < 4; q++) {
            float4 a = vp[lane * 4 + q];
            vA[4*q] = a.x; vA[4*q+1] = a.y; vA[4*q+2] = a.z; vA[4*q+3] = a.w;
            float4 c = vp[(lane + 32) * 4 + q];
            vB[4*q] = c.x; vB[4*q+1] = c.y; vB[4*q+2] = c.z; vB[4*q+3] = c.w;
        }
        if (SECOND) {
            const float4* vq = (const float4*)(g_v1 + b * K_);
            #pragma unroll
            for (int q = 0; q < 4; q++) {
                float4 a = vq[lane * 4 + q];
                vA[4*q] += a.x; vA[4*q+1] += a.y; vA[4*q+2] += a.z; vA[4*q+3] += a.w;
                float4 c = vq[(lane + 32) * 4 + q];
                vB[4*q] += c.x; vB[4*q+1] += c.y; vB[4*q+2] += c.z; vB[4*q+3] += c.w;
            }
        }
        #pragma unroll
        for (int q = 0; q < 8; q++) {
            vA2[q] = __floats2half2_rn(vA[2*q], vA[2*q+1]);
            vB2[q] = __floats2half2_rn(vB[2*q], vB[2*q+1]);
        }
    }

    const uint4* base = (const uint4*)(g_uhat + ((size_t)b * IC_ + i0) * K_);
    const int ROWQ = K_ / 8;                       // uint4 per i-row (fp16)

    __half2 sA2[8], sB2[8];
    #pragma unroll
    for (int q = 0; q < 8; q++) {
        sA2[q] = __floats2half2_rn(0.f, 0.f);
        sB2[q] = __floats2half2_rn(0.f, 0.f);
    }

    // ---- preload pair 0 (rows 0,1): 8 named uint4 ----
    uint4 cA0, cA1, cB0, cB1, dA0, dA1, dB0, dB1;
    {
        const uint4* r0 = base;
        const uint4* r1 = base + ROWQ;
        cA0 = r0[lane * 2];      cA1 = r0[lane * 2 + 1];
        cB0 = r0[64 + lane * 2]; cB1 = r0[64 + lane * 2 + 1];
        dA0 = r1[lane * 2];      dA1 = r1[lane * 2 + 1];
        dB0 = r1[64 + lane * 2]; dB1 = r1[64 + lane * 2 + 1];
    }

    #pragma unroll 1
    for (int it = 0; it < 32; it++) {              // pair = rows 2it, 2it+1
        // ---- prefetch next pair (clamped; last iter re-loads harmlessly) --
        const int itn = (it < 31) ? (it + 1) : it;
        const uint4* p0 = base + (size_t)(2 * itn) * ROWQ;
        const uint4* p1 = p0 + ROWQ;
        uint4 nA0 = p0[lane * 2];      uint4 nA1 = p0[lane * 2 + 1];
        uint4 nB0 = p0[64 + lane * 2]; uint4 nB1 = p0[64 + lane * 2 + 1];
        uint4 mA0 = p1[lane * 2];      uint4 mA1 = p1[lane * 2 + 1];
        uint4 mB0 = p1[64 + lane * 2]; uint4 mB1 = p1[64 + lane * 2 + 1];

        // ---- dots for both current rows (half2) ----
        const __half2* hcA0 = (const __half2*)&cA0;
        const __half2* hcA1 = (const __half2*)&cA1;
        const __half2* hcB0 = (const __half2*)&cB0;
        const __half2* hcB1 = (const __half2*)&cB1;
        const __half2* hdA0 = (const __half2*)&dA0;
        const __half2* hdA1 = (const __half2*)&dA1;
        const __half2* hdB0 = (const __half2*)&dB0;
        const __half2* hdB1 = (const __half2*)&dB1;

        __half2 e0h = __floats2half2_rn(0.f, 0.f);
        __half2 e1h = __floats2half2_rn(0.f, 0.f);
        __half2 e2h = __floats2half2_rn(0.f, 0.f);
        __half2 e3h = __floats2half2_rn(0.f, 0.f);
        #pragma unroll
        for (int q = 0; q < 4; q++) {
            e0h = __hfma2(hcA0[q], vA2[q],     e0h);
            e0h = __hfma2(hcA1[q], vA2[4 + q], e0h);
            e1h = __hfma2(hcB0[q], vB2[q],     e1h);
            e1h = __hfma2(hcB1[q], vB2[4 + q], e1h);
            e2h = __hfma2(hdA0[q], vA2[q],     e2h);
            e2h = __hfma2(hdA1[q], vA2[4 + q], e2h);
            e3h = __hfma2(hdB0[q], vB2[q],     e3h);
            e3h = __hfma2(hdB1[q], vB2[4 + q], e3h);
        }
        float2 f0 = __half22float2(e0h), f1 = __half22float2(e1h);
        float2 f2 = __half22float2(e2h), f3 = __half22float2(e3h);
        const float a0 = f0.x + f0.y, a1 = f1.x + f1.y;
        const float a2 = f2.x + f2.y, a3 = f3.x + f3.y;

        const float ex0 = __expf(a0), ex1 = __expf(a1);
        const float ex2 = __expf(a2), ex3 = __expf(a3);
        float z0 = ex0 + ex1;                     // row0 softmax denom
        float z1 = ex2 + ex3;                     // row1 softmax denom
        // interleaved shuffle chains (independent -> overlap SHFL latency)
        #pragma unroll
        for (int off = 16; off >= 1; off >>= 1) {
            z0 += __shfl_xor_sync(0xffffffffu, z0, off);
            z1 += __shfl_xor_sync(0xffffffffu, z1, off);
        }
        const float rz0 = __fdividef(1.0f, z0);
        const float rz1 = __fdividef(1.0f, z1);
        const __half2 c00 = __float2half2_rn(ex0 * rz0);
        const __half2 c01 = __float2half2_rn(ex1 * rz0);
        const __half2 c10 = __float2half2_rn(ex2 * rz1);
        const __half2 c11 = __float2half2_rn(ex3 * rz1);

        // ---- accumulate both rows ----
        #pragma unroll
        for (int q = 0; q < 4; q++) {
            sA2[q]     = __hfma2(c00, hcA0[q], sA2[q]);
            sA2[4 + q] = __hfma2(c00, hcA1[q], sA2[4 + q]);
            sB2[q]     = __hfma2(c01, hcB0[q], sB2[q]);
            sB2[4 + q] = __hfma2(c01, hcB1[q], sB2[4 + q]);
            sA2[q]     = __hfma2(c10, hdA0[q], sA2[q]);
            sA2[4 + q] = __hfma2(c10, hdA1[q], sA2[4 + q]);
            sB2[q]     = __hfma2(c11, hdB0[q], sB2[q]);
            sB2[4 + q] = __hfma2(c11, hdB1[q], sB2[4 + q]);
        }

        // ---- rotate pipeline ----
        cA0 = nA0; cA1 = nA1; cB0 = nB0; cB1 = nB1;
        dA0 = mA0; dA1 = mA1; dB0 = mB0; dB1 = mB1;
    }

    float* sp = g_s[SECOND ? 2 : 1] + b * K_;
    #pragma unroll
    for (int q = 0; q < 8; q++) {
        float2 fa = __half22float2(sA2[q]);
        atomicAdd(sp + lane * 16 + 2 * q,     fa.x);
        atomicAdd(sp + lane * 16 + 2 * q + 1, fa.y);
        float2 fb = __half22float2(sB2[q]);
        atomicAdd(sp + (lane + 32) * 16 + 2 * q,     fb.x);
        atomicAdd(sp + (lane + 32) * 16 + 2 * q + 1, fb.y);
    }
}

// ---------------- launcher -------------------------------------------------
extern "C" void kernel_launch(void* const* d_in, const int* in_sizes, int n_in,
                              void* d_out, int out_size) {
    const float* x    = (const float*)d_in[0];   // [64,2048,16]
    const float* W    = (const float*)d_in[1];   // [2048,16,1024]
    const float* bias = (const float*)d_in[2];   // [64,16] -> 1024
    float* out = (float*)d_out;                  // [64,64,16]

    k_init<<<192, 1024>>>(bias);                         // s0,s1,s2 = bias
    k_project<<<dim3(2, 2, 64), 256>>>(x, W);            // u_hat(fp16) + s0 mean
    k_squash<<<B_, 1024>>>(0, out);                      // v0

    k_route<false><<<dim3(16, B_), 64>>>();              // s1
    k_squash<<<B_, 1024>>>(1, out);                      // v1

    k_route<true><<<dim3(16, B_), 64>>>();               // s2
    k_squash<<<B_, 1024>>>(2, out);                      // v2 -> out
}